// round 7
// baseline (speedup 1.0000x reference)
#include <cuda_runtime.h>
#include <cstdint>

#define NN 1000000
#define NE 8000000
#define EMB 64

// Scratch (no cudaMalloc allowed): projected features h [NN, 64] and softmax denominators [2, NN]
__device__ float g_h[(size_t)NN * EMB];
__device__ float g_denom[2 * NN];

__device__ __forceinline__ float leaky(float x) { return fmaxf(x, 0.01f * x); }

// ---- packed f32x2 helpers (sm_103a) ----
__device__ __forceinline__ unsigned long long pack2(float x, float y) {
    unsigned long long u;
    asm("mov.b64 %0, {%1, %2};" : "=l"(u) : "r"(__float_as_uint(x)), "r"(__float_as_uint(y)));
    return u;
}
__device__ __forceinline__ void unpack2(unsigned long long u, float& x, float& y) {
    unsigned lo, hi;
    asm("mov.b64 {%0, %1}, %2;" : "=r"(lo), "=r"(hi) : "l"(u));
    x = __uint_as_float(lo);
    y = __uint_as_float(hi);
}
__device__ __forceinline__ unsigned long long fma2(unsigned long long a, unsigned long long b,
                                                   unsigned long long c) {
    unsigned long long d;
    asm("fma.rn.f32x2 %0, %1, %2, %3;" : "=l"(d) : "l"(a), "l"(b), "l"(c));
    return d;
}

// ============================================================================
// K1: projection  h = leaky_relu(ego @ Wfull + bfull)
//   Wfull[k][D] with D = c*32 + d  ->  W[c][k][d]  (W is [2][64][32])
//   One thread per node, 64 outputs as 32 packed f32x2 accumulators.
// ============================================================================
__global__ __launch_bounds__(128) void proj_kernel(const float* __restrict__ ego,
                                                   const float* __restrict__ W,
                                                   const float* __restrict__ b) {
    __shared__ unsigned long long sW[64 * 32];  // sW[k*32+j] = (Wfull[k][2j], Wfull[k][2j+1])
    __shared__ unsigned long long sB[32];

    for (int i = threadIdx.x; i < 64 * 32; i += 128) {
        int k = i >> 5, j = i & 31;
        int D = 2 * j, ch = D >> 5, d = D & 31;
        const float2 v = *(const float2*)(W + ch * 64 * 32 + k * 32 + d);
        sW[i] = pack2(v.x, v.y);
    }
    if (threadIdx.x < 32) {
        int j = threadIdx.x;
        int D = 2 * j, ch = D >> 5, d = D & 31;
        const float2 v = *(const float2*)(b + ch * 32 + d);
        sB[j] = pack2(v.x, v.y);
    }
    __syncthreads();

    int n = blockIdx.x * 128 + threadIdx.x;
    if (n >= NN) return;

    unsigned long long acc[32];
#pragma unroll
    for (int j = 0; j < 32; j++) acc[j] = sB[j];

    const float4* er = (const float4*)(ego + (size_t)n * EMB);
#pragma unroll 4
    for (int kk = 0; kk < 16; kk++) {
        float4 ev = er[kk];
        float es[4] = {ev.x, ev.y, ev.z, ev.w};
#pragma unroll
        for (int t = 0; t < 4; t++) {
            int k = kk * 4 + t;
            unsigned long long ee = pack2(es[t], es[t]);
#pragma unroll
            for (int j = 0; j < 32; j++) acc[j] = fma2(ee, sW[k * 32 + j], acc[j]);
        }
    }

    float4* outp = (float4*)(g_h + (size_t)n * EMB);
#pragma unroll
    for (int j = 0; j < 32; j += 2) {
        float a0, a1, c0, c1;
        unpack2(acc[j], a0, a1);
        unpack2(acc[j + 1], c0, c1);
        outp[j >> 1] = make_float4(leaky(a0), leaky(a1), leaky(c0), leaky(c1));
    }
}

// ============================================================================
// K2: fused edge pass (one warp per edge).
//   Per edge: gather h[row], h[col] (256B each), compute both channel dots via
//   16-lane butterfly reduce, ex = exp(leaky(dot)) (no max-subtraction needed:
//   logits are bounded ~<25, and the +EPS shift is <=1e-10 relative either way),
//   red.add denom, red.add.v2 message ex*h_col into out[row].
// ============================================================================
__global__ __launch_bounds__(256) void edge_kernel(const int* __restrict__ row,
                                                   const int* __restrict__ col,
                                                   float* __restrict__ out) {
    int e = blockIdx.x * 8 + (threadIdx.x >> 5);
    if (e >= NE) return;
    int lane = threadIdx.x & 31;
    int r = __ldg(row + e);
    int c = __ldg(col + e);

    const float2* hr = (const float2*)(g_h + (size_t)r * EMB);
    const float2* hc = (const float2*)(g_h + (size_t)c * EMB);
    float2 a = hr[lane];   // dims 2*lane, 2*lane+1  (lanes 0-15 = ch0, 16-31 = ch1)
    float2 m = hc[lane];

    float p = a.x * m.x + a.y * m.y;
    // reduce independently within each 16-lane half (masks < 16 stay in-half)
    p += __shfl_xor_sync(0xffffffffu, p, 1);
    p += __shfl_xor_sync(0xffffffffu, p, 2);
    p += __shfl_xor_sync(0xffffffffu, p, 4);
    p += __shfl_xor_sync(0xffffffffu, p, 8);

    float ex = __expf(leaky(p));  // every lane holds its channel's ex

    if ((lane & 15) == 0) {
        float* dptr = g_denom + (lane >> 4) * NN + r;
        asm volatile("red.global.add.f32 [%0], %1;" ::"l"(dptr), "f"(ex) : "memory");
    }

    float* dst = out + (size_t)r * EMB + 2 * lane;
    asm volatile("red.global.add.v2.f32 [%0], {%1, %2};" ::"l"(dst), "f"(ex * m.x),
                 "f"(ex * m.y)
                 : "memory");
}

// ============================================================================
// K3: out[n][D] /= (denom[ch][n] + 1e-10)   (== multiplying by alpha normalizer)
// ============================================================================
__global__ __launch_bounds__(256) void finalize_kernel(float* __restrict__ out) {
    int i = blockIdx.x * 256 + threadIdx.x;  // over NN*16 float4s
    if (i >= NN * 16) return;
    int n = i >> 4;
    int ch = (i >> 3) & 1;
    float s = 1.0f / (g_denom[ch * NN + n] + 1e-10f);
    float4* o4 = (float4*)out;
    float4 v = o4[i];
    v.x *= s;
    v.y *= s;
    v.z *= s;
    v.w *= s;
    o4[i] = v;
}

extern "C" void kernel_launch(void* const* d_in, const int* in_sizes, int n_in,
                              void* d_out, int out_size) {
    const float* ego = (const float*)d_in[0];  // [NN, 64]
    const float* W = (const float*)d_in[1];    // [2, 64, 32]
    const float* b = (const float*)d_in[2];    // [2, 1, 32]
    const int* row = (const int*)d_in[3];      // [NE]
    const int* col = (const int*)d_in[4];      // [NE]
    float* out = (float*)d_out;                // [NN, 64]

    void* denom_ptr = nullptr;
    cudaGetSymbolAddress(&denom_ptr, g_denom);

    // out is poisoned 0xAA each run; we accumulate into it, so zero first.
    cudaMemsetAsync(out, 0, (size_t)NN * EMB * sizeof(float));
    cudaMemsetAsync(denom_ptr, 0, 2 * NN * sizeof(float));

    proj_kernel<<<(NN + 127) / 128, 128>>>(ego, W, b);
    edge_kernel<<<NE / 8, 256>>>(row, col, out);
    finalize_kernel<<<(NN * 16 + 255) / 256, 256>>>(out);
}

// round 9
// speedup vs baseline: 1.9685x; 1.9685x over previous
#include <cuda_runtime.h>
#include <cstdint>

#define NN 1000000
#define NE 8000000
#define EMB 64
#define NBLK 977            // ceil(NN/1024)

// Scratch (no cudaMalloc allowed)
__device__ float g_h[(size_t)NN * EMB];   // projected features [NN,64]
__device__ int g_off[NN + 1];             // CSR row offsets (exclusive)
__device__ int g_cursor[NN];              // counts, then scatter cursors
__device__ int g_scol[NE];                // col indices sorted by row
__device__ int g_blocksums[NBLK];

__device__ __forceinline__ float leaky(float x) { return fmaxf(x, 0.01f * x); }

// ---- packed f32x2 helpers (sm_103a) ----
__device__ __forceinline__ unsigned long long pack2(float x, float y) {
    unsigned long long u;
    asm("mov.b64 %0, {%1, %2};" : "=l"(u) : "r"(__float_as_uint(x)), "r"(__float_as_uint(y)));
    return u;
}
__device__ __forceinline__ void unpack2(unsigned long long u, float& x, float& y) {
    unsigned lo, hi;
    asm("mov.b64 {%0, %1}, %2;" : "=r"(lo), "=r"(hi) : "l"(u));
    x = __uint_as_float(lo);
    y = __uint_as_float(hi);
}
__device__ __forceinline__ unsigned long long fma2(unsigned long long a, unsigned long long b,
                                                   unsigned long long c) {
    unsigned long long d;
    asm("fma.rn.f32x2 %0, %1, %2, %3;" : "=l"(d) : "l"(a), "l"(b), "l"(c));
    return d;
}

// ============================================================================
// K1: projection  h = leaky_relu(ego @ Wfull + bfull)
//   sW2[k][j2] = ulonglong2 = packed f32x2 pairs for outputs (4j2..4j2+3) at k.
//   LDS.128 halves the shared-load instruction count vs LDS.64.
// ============================================================================
__global__ __launch_bounds__(128) void proj_kernel(const float* __restrict__ ego,
                                                   const float* __restrict__ W,
                                                   const float* __restrict__ b) {
    __shared__ ulonglong2 sW2[64 * 16];
    __shared__ ulonglong2 sB2[16];

    for (int i = threadIdx.x; i < 64 * 16; i += 128) {
        int k = i >> 4, j2 = i & 15;
        int ch = j2 >> 3;              // 4*j2 >= 32 ?
        int d = (4 * j2) & 31;
        const float4 v = *(const float4*)(W + ch * 64 * 32 + k * 32 + d);
        sW2[i] = make_ulonglong2(pack2(v.x, v.y), pack2(v.z, v.w));
    }
    if (threadIdx.x < 16) {
        int j2 = threadIdx.x;
        int ch = j2 >> 3;
        int d = (4 * j2) & 31;
        const float4 v = *(const float4*)(b + ch * 32 + d);
        sB2[j2] = make_ulonglong2(pack2(v.x, v.y), pack2(v.z, v.w));
    }
    __syncthreads();

    int n = blockIdx.x * 128 + threadIdx.x;
    if (n >= NN) return;

    unsigned long long acc[32];
#pragma unroll
    for (int j2 = 0; j2 < 16; j2++) {
        ulonglong2 bv = sB2[j2];
        acc[2 * j2] = bv.x;
        acc[2 * j2 + 1] = bv.y;
    }

    const float4* er = (const float4*)(ego + (size_t)n * EMB);
#pragma unroll 4
    for (int kk = 0; kk < 16; kk++) {
        float4 ev = er[kk];
        float es[4] = {ev.x, ev.y, ev.z, ev.w};
#pragma unroll
        for (int t = 0; t < 4; t++) {
            unsigned long long ee = pack2(es[t], es[t]);
            const ulonglong2* wr = sW2 + (kk * 4 + t) * 16;
#pragma unroll
            for (int j2 = 0; j2 < 16; j2++) {
                ulonglong2 wv = wr[j2];
                acc[2 * j2] = fma2(ee, wv.x, acc[2 * j2]);
                acc[2 * j2 + 1] = fma2(ee, wv.y, acc[2 * j2 + 1]);
            }
        }
    }

    float4* outp = (float4*)(g_h + (size_t)n * EMB);
#pragma unroll
    for (int j = 0; j < 32; j += 2) {
        float a0, a1, c0, c1;
        unpack2(acc[j], a0, a1);
        unpack2(acc[j + 1], c0, c1);
        outp[j >> 1] = make_float4(leaky(a0), leaky(a1), leaky(c0), leaky(c1));
    }
}

// ============================================================================
// CSR build: count -> 2-level exclusive scan -> scatter cols into row order
// ============================================================================
__global__ __launch_bounds__(256) void count_kernel(const int* __restrict__ row) {
    int i = blockIdx.x * 256 + threadIdx.x;  // over NE/4
    if (i >= NE / 4) return;
    int4 r = ((const int4*)row)[i];
    atomicAdd(&g_cursor[r.x], 1);
    atomicAdd(&g_cursor[r.y], 1);
    atomicAdd(&g_cursor[r.z], 1);
    atomicAdd(&g_cursor[r.w], 1);
}

__global__ __launch_bounds__(1024) void scan1_kernel() {
    __shared__ int s[1024];
    int t = threadIdx.x;
    int i = blockIdx.x * 1024 + t;
    int v = (i < NN) ? g_cursor[i] : 0;
    s[t] = v;
    __syncthreads();
#pragma unroll
    for (int d = 1; d < 1024; d <<= 1) {
        int x = (t >= d) ? s[t - d] : 0;
        __syncthreads();
        s[t] += x;
        __syncthreads();
    }
    if (i < NN) g_off[i] = s[t] - v;  // exclusive within block
    if (t == 1023) g_blocksums[blockIdx.x] = s[1023];
}

__global__ __launch_bounds__(1024) void scan2_kernel() {
    __shared__ int s[1024];
    int t = threadIdx.x;
    int v = (t < NBLK) ? g_blocksums[t] : 0;
    s[t] = v;
    __syncthreads();
#pragma unroll
    for (int d = 1; d < 1024; d <<= 1) {
        int x = (t >= d) ? s[t - d] : 0;
        __syncthreads();
        s[t] += x;
        __syncthreads();
    }
    if (t < NBLK) g_blocksums[t] = s[t] - v;  // exclusive block bases
}

__global__ __launch_bounds__(256) void scan3_kernel() {
    int i = blockIdx.x * 256 + threadIdx.x;
    if (i < NN) {
        int o = g_off[i] + g_blocksums[i >> 10];
        g_off[i] = o;
        g_cursor[i] = o;  // scatter cursors start at row base
    }
    if (i == 0) g_off[NN] = NE;
}

__global__ __launch_bounds__(256) void scatter_kernel(const int* __restrict__ row,
                                                      const int* __restrict__ col) {
    int i = blockIdx.x * 256 + threadIdx.x;  // over NE/4
    if (i >= NE / 4) return;
    int4 r = ((const int4*)row)[i];
    int4 c = ((const int4*)col)[i];
    int p;
    p = atomicAdd(&g_cursor[r.x], 1); g_scol[p] = c.x;
    p = atomicAdd(&g_cursor[r.y], 1); g_scol[p] = c.y;
    p = atomicAdd(&g_cursor[r.z], 1); g_scol[p] = c.z;
    p = atomicAdd(&g_cursor[r.w], 1); g_scol[p] = c.w;
}

// ============================================================================
// K2: per-row reduction. One warp per destination row: load h[row] once,
//   stream h[col] for its edges (depth-1 prefetch), accumulate denom and
//   ex*h_col in registers, single coalesced output write with the 1/(den+eps)
//   normalizer fused. No output atomics, no finalize pass, no out memset.
//   (Max-subtraction elided: logits bounded << fp32 exp overflow; EPS shift
//    <= 1e-10 relative either way.)
// ============================================================================
__global__ __launch_bounds__(256) void row_kernel(float* __restrict__ out) {
    int w = (blockIdx.x * 256 + threadIdx.x) >> 5;  // row id
    if (w >= NN) return;
    int lane = threadIdx.x & 31;
    int beg = g_off[w];
    int end = g_off[w + 1];

    const float2* hb = (const float2*)g_h;
    float2 a = hb[w * 32 + lane];  // lanes 0-15: ch0 dims, 16-31: ch1 dims
    float ax = 0.0f, ay = 0.0f, den = 0.0f;

    if (beg < end) {
        int c0 = __ldg(g_scol + beg);
        float2 m0 = hb[c0 * 32 + lane];
        for (int e = beg; e < end;) {
            float2 m = m0;
            ++e;
            if (e < end) {  // prefetch next neighbor's features
                int c1 = __ldg(g_scol + e);
                m0 = hb[c1 * 32 + lane];
            }
            float p = a.x * m.x + a.y * m.y;
            // reduce within each 16-lane half (one channel per half)
            p += __shfl_xor_sync(0xffffffffu, p, 1);
            p += __shfl_xor_sync(0xffffffffu, p, 2);
            p += __shfl_xor_sync(0xffffffffu, p, 4);
            p += __shfl_xor_sync(0xffffffffu, p, 8);
            float ex = __expf(leaky(p));
            den += ex;
            ax = fmaf(ex, m.x, ax);
            ay = fmaf(ex, m.y, ay);
        }
    }
    float s = 1.0f / (den + 1e-10f);  // zero-degree rows: acc=0 -> out=0
    ((float2*)out)[w * 32 + lane] = make_float2(ax * s, ay * s);
}

extern "C" void kernel_launch(void* const* d_in, const int* in_sizes, int n_in,
                              void* d_out, int out_size) {
    const float* ego = (const float*)d_in[0];  // [NN, 64]
    const float* W = (const float*)d_in[1];    // [2, 64, 32]
    const float* b = (const float*)d_in[2];    // [2, 1, 32]
    const int* row = (const int*)d_in[3];      // [NE]
    const int* col = (const int*)d_in[4];      // [NE]
    float* out = (float*)d_out;                // [NN, 64]

    void* cursor_ptr = nullptr;
    cudaGetSymbolAddress(&cursor_ptr, g_cursor);
    cudaMemsetAsync(cursor_ptr, 0, NN * sizeof(int));

    count_kernel<<<(NE / 4 + 255) / 256, 256>>>(row);
    scan1_kernel<<<NBLK, 1024>>>();
    scan2_kernel<<<1, 1024>>>();
    scan3_kernel<<<(NN + 255) / 256, 256>>>();

    proj_kernel<<<(NN + 127) / 128, 128>>>(ego, W, b);

    scatter_kernel<<<(NE / 4 + 255) / 256, 256>>>(row, col);
    row_kernel<<<(NN * 32 + 255) / 256, 256>>>(out);
}